// round 12
// baseline (speedup 1.0000x reference)
#include <cuda_runtime.h>
#include <cuda_bf16.h>

typedef unsigned int u32; typedef unsigned short u16;

#define B_ 8
#define N_ 16384
#define D_ 128
#define K_ 128
#define CH 128
#define CPB 19
#define GRID (B_*CPB)
#define NT 512
#define CHUNKS_PER_B 128

#define RS 272                 /* tile row stride bytes = 68 u32 = 136 u16 */
#define TNM 34816              /* 128-row tile bytes */
#define OFF_X2  0
#define OFF_MS  512            /* (m,s) exchange: 2 halves x 128 rows x float2 */
#define OFF_SM2 2560
#define OFF_SSC 3072
#define OFF_SS  3584
#define OFF_CS  4096           /* colsum[128] */
#define OFF_CHI 4608
#define OFF_CLO (OFF_CHI+1*TNM)
#define OFF_XHI (OFF_CHI+2*TNM)
#define OFF_XLO (OFF_CHI+3*TNM)
#define OFF_AHI (OFF_CHI+4*TNM)
#define SMEM_BYTES (OFF_CHI+5*TNM)   /* 178688 */

__device__ float g_partial[(size_t)GRID*K_*D_];

static __device__ __forceinline__ u32 cvta_s(const void* p){
    u32 a; asm("{ .reg .u64 t; cvta.to.shared.u64 t, %1; cvt.u32.u64 %0, t; }":"=r"(a):"l"(p)); return a;
}
static __device__ __forceinline__ void ldm4(u32&r0,u32&r1,u32&r2,u32&r3,u32 a){
    asm volatile("ldmatrix.sync.aligned.m8n8.x4.shared.b16 {%0,%1,%2,%3}, [%4];"
        : "=r"(r0),"=r"(r1),"=r"(r2),"=r"(r3) : "r"(a));
}
static __device__ __forceinline__ void ldm4t(u32&r0,u32&r1,u32&r2,u32&r3,u32 a){
    asm volatile("ldmatrix.sync.aligned.m8n8.x4.trans.shared.b16 {%0,%1,%2,%3}, [%4];"
        : "=r"(r0),"=r"(r1),"=r"(r2),"=r"(r3) : "r"(a));
}
static __device__ __forceinline__ void ldm2t(u32&r0,u32&r1,u32 a){
    asm volatile("ldmatrix.sync.aligned.m8n8.x2.trans.shared.b16 {%0,%1}, [%2];"
        : "=r"(r0),"=r"(r1) : "r"(a));
}
static __device__ __forceinline__ void mma_bf(float* c, u32 a0,u32 a1,u32 a2,u32 a3, u32 b0,u32 b1){
    asm volatile("mma.sync.aligned.m16n8k16.row.col.f32.bf16.bf16.f32 "
        "{%0,%1,%2,%3}, {%4,%5,%6,%7}, {%8,%9}, {%0,%1,%2,%3};"
        : "+f"(c[0]),"+f"(c[1]),"+f"(c[2]),"+f"(c[3])
        : "r"(a0),"r"(a1),"r"(a2),"r"(a3),"r"(b0),"r"(b1));
}
static __device__ __forceinline__ void splitbf(float x, u16& h, u16& l){
    __nv_bfloat16 bh = __float2bfloat16(x);
    float r = x - __bfloat162float(bh);
    h = __bfloat16_as_ushort(bh);
    l = __bfloat16_as_ushort(__float2bfloat16(r));
}
static __device__ __forceinline__ u16 tobf(float x){
    return __bfloat16_as_ushort(__float2bfloat16(x));
}
static __device__ __forceinline__ u32 pkh(u16 a, u16 b){ return (u32)a | ((u32)b<<16); }

__global__ __launch_bounds__(NT, 1)
void vq_mma_kernel(const float* __restrict__ X, const float* __restrict__ C,
                   const float* __restrict__ S)
{
    extern __shared__ char sm[];
    const u32 smb = cvta_s(sm);
    const int tid = threadIdx.x, w = tid>>5, l = tid&31;
    const int rg = w&7, kh = w>>3;     // phase-1 tile: rows 16rg..+15, k-cols 64kh..+63
    const int kg = w&7, dh = w>>3;     // phase-3 tile: k-rows 16kg..+15, d-cols 64dh..+63

    // ones column in XHI padding: u16 col 128 = bf16 1.0, cols 129..135 = 0
    if (tid < 128){
        u32* row = (u32*)(sm+OFF_XHI) + tid*68;
        row[64] = 0x00003F80u; row[65] = 0u; row[66] = 0u; row[67] = 0u;
    }

    // ---- C -> Chi/Clo (k-major) + ||c||^2  (4 threads per row) ----
    {
        int k = tid>>2, q = tid&3;
        const float* cr = C + k*D_ + q*32;
        u32* dhp = (u32*)(sm+OFF_CHI) + k*68 + q*16;
        u32* dlp = (u32*)(sm+OFF_CLO) + k*68 + q*16;
        float c2 = 0.f;
        #pragma unroll
        for (int i = 0; i < 8; i++){
            float4 v = *(const float4*)(cr + 4*i);
            float xs[4] = {v.x,v.y,v.z,v.w};
            u16 hb[4], lb[4];
            #pragma unroll
            for (int e = 0; e < 4; e++){ c2 += xs[e]*xs[e]; splitbf(xs[e], hb[e], lb[e]); }
            dhp[2*i]   = pkh(hb[0],hb[1]);  dhp[2*i+1] = pkh(hb[2],hb[3]);
            dlp[2*i]   = pkh(lb[0],lb[1]);  dlp[2*i+1] = pkh(lb[2],lb[3]);
        }
        c2 += __shfl_xor_sync(0xffffffffu, c2, 1);
        c2 += __shfl_xor_sync(0xffffffffu, c2, 2);
        if (q == 0) ((float*)(sm+OFF_X2))[k] = c2;
    }
    __syncthreads();
    if (tid < K_){
        float s = S[tid], c2 = ((float*)(sm+OFF_X2))[tid];
        ((float*)(sm+OFF_SM2))[tid] = -2.f*s;
        ((float*)(sm+OFF_SSC))[tid] = s*c2;
        ((float*)(sm+OFF_SS ))[tid] = s;
    }
    __syncthreads();

    const int bb = blockIdx.x / CPB, tt = blockIdx.x % CPB;
    const int base = CHUNKS_PER_B / CPB, rem = CHUNKS_PER_B % CPB;
    const int cnt = base + (tt < rem ? 1 : 0);
    const int st  = tt*base + (tt < rem ? tt : rem);

    // lane address bases
    const u32 aX1 = smb + OFF_XHI + (u32)((16*rg + (l&15))*RS + 16*(l>>4));                  // P1 A
    const u32 aC  = smb + OFF_CHI + (u32)((64*kh + (l&7) + 8*(l>>4))*RS + 16*((l>>3)&1));    // P1 B
    const u32 aAt = smb + OFF_AHI + (u32)(((l&7) + 8*(l>>4))*RS + 32*kg + 16*((l>>3)&1));    // P3 A trans
    const u32 aXt = smb + OFF_XHI + (u32)(((l&7) + 8*((l>>3)&1))*RS + 128*dh + 16*(l>>4));   // P3 B trans
    const u32 aOn = smb + OFF_XHI + (u32)(((l&7) + 8*((l>>3)&1))*RS + 256);                  // ones col trans

    float Eg[8][4];
    float cs[4];
    cs[0]=cs[1]=cs[2]=cs[3]=0.f;
    #pragma unroll
    for (int j = 0; j < 8; j++){ Eg[j][0]=Eg[j][1]=Eg[j][2]=Eg[j][3]=0.f; }

    float2* ms2 = (float2*)(sm+OFF_MS);

    // prefetch pointer for this thread's 32 floats of a chunk
    const float* Xb = X + (size_t)bb*N_*D_ + (size_t)(tid>>2)*D_ + (size_t)(tid&3)*32;

    // prefetch chunk 0
    float4 pf[8];
    {
        const float* xr = Xb + (size_t)st*CH*D_;
        #pragma unroll
        for (int i = 0; i < 8; i++) pf[i] = *(const float4*)(xr + 4*i);
    }

    for (int ci = 0; ci < cnt; ci++){
        __syncthreads();   // prev phase-3 reads done before overwrite

        // ---- convert prefetched X regs -> Xhi/Xlo + x2 ----
        {
            int n = tid>>2, q = tid&3;
            u32* dhp = (u32*)(sm+OFF_XHI) + n*68 + q*16;
            u32* dlp = (u32*)(sm+OFF_XLO) + n*68 + q*16;
            float x2 = 0.f;
            #pragma unroll
            for (int i = 0; i < 8; i++){
                float xs[4] = {pf[i].x,pf[i].y,pf[i].z,pf[i].w};
                u16 hb[4], lb[4];
                #pragma unroll
                for (int e = 0; e < 4; e++){ x2 += xs[e]*xs[e]; splitbf(xs[e], hb[e], lb[e]); }
                dhp[2*i]   = pkh(hb[0],hb[1]);  dhp[2*i+1] = pkh(hb[2],hb[3]);
                dlp[2*i]   = pkh(lb[0],lb[1]);  dlp[2*i+1] = pkh(lb[2],lb[3]);
            }
            x2 += __shfl_xor_sync(0xffffffffu, x2, 1);
            x2 += __shfl_xor_sync(0xffffffffu, x2, 2);
            if (q == 0) ((float*)(sm+OFF_X2))[n] = x2;
        }
        __syncthreads();

        // ---- phase 1: logits (16 rows x 64 k per warp), 3-pass split ----
        float Dg[8][4];
        #pragma unroll
        for (int j = 0; j < 8; j++){ Dg[j][0]=Dg[j][1]=Dg[j][2]=Dg[j][3]=0.f; }

        #pragma unroll 1
        for (int s = 0; s < 8; s++){
            u32 so = 32u*s;
            u32 ah0,ah1,ah2,ah3, al0,al1,al2,al3;
            ldm4(ah0,ah1,ah2,ah3, aX1 + so);
            ldm4(al0,al1,al2,al3, aX1 + TNM + so);
            #pragma unroll
            for (int p = 0; p < 4; p++){
                u32 bo = aC + (u32)(p*16*RS) + so;
                u32 bh0,bh1,bh2,bh3, bl0,bl1,bl2,bl3;
                ldm4(bh0,bh1,bh2,bh3, bo);
                ldm4(bl0,bl1,bl2,bl3, bo + TNM);
                mma_bf(Dg[2*p],   ah0,ah1,ah2,ah3, bh0,bh1);
                mma_bf(Dg[2*p],   ah0,ah1,ah2,ah3, bl0,bl1);
                mma_bf(Dg[2*p],   al0,al1,al2,al3, bh0,bh1);
                mma_bf(Dg[2*p+1], ah0,ah1,ah2,ah3, bh2,bh3);
                mma_bf(Dg[2*p+1], ah0,ah1,ah2,ah3, bl2,bl3);
                mma_bf(Dg[2*p+1], al0,al1,al2,al3, bh2,bh3);
            }
        }

        // ---- softmax: scale, per-half (m,s), exchange, normalize, write A_hi ----
        {
            float x2v[2], mh[2], sh[2];
            x2v[0] = ((float*)(sm+OFF_X2))[16*rg + (l>>2)];
            x2v[1] = ((float*)(sm+OFF_X2))[16*rg + (l>>2) + 8];

            #pragma unroll
            for (int j = 0; j < 8; j++){
                int c0 = 64*kh + 8*j + 2*(l&3);
                float2 m2 = *(const float2*)(sm + OFF_SM2 + c0*4);
                float2 sc = *(const float2*)(sm + OFF_SSC + c0*4);
                float2 sv = *(const float2*)(sm + OFF_SS  + c0*4);
                Dg[j][0] = fmaf(m2.x, Dg[j][0], fmaf(sv.x, x2v[0], sc.x));
                Dg[j][1] = fmaf(m2.y, Dg[j][1], fmaf(sv.y, x2v[0], sc.y));
                Dg[j][2] = fmaf(m2.x, Dg[j][2], fmaf(sv.x, x2v[1], sc.x));
                Dg[j][3] = fmaf(m2.y, Dg[j][3], fmaf(sv.y, x2v[1], sc.y));
            }

            float ma = -1e30f, mb = -1e30f;
            #pragma unroll
            for (int j = 0; j < 8; j++){
                ma = fmaxf(ma, fmaxf(Dg[j][0], Dg[j][1]));
                mb = fmaxf(mb, fmaxf(Dg[j][2], Dg[j][3]));
            }
            ma = fmaxf(ma, __shfl_xor_sync(0xffffffffu, ma, 1));
            ma = fmaxf(ma, __shfl_xor_sync(0xffffffffu, ma, 2));
            mb = fmaxf(mb, __shfl_xor_sync(0xffffffffu, mb, 1));
            mb = fmaxf(mb, __shfl_xor_sync(0xffffffffu, mb, 2));
            float sa = 0.f, sb = 0.f;
            #pragma unroll
            for (int j = 0; j < 8; j++){
                Dg[j][0] = __expf(Dg[j][0]-ma);  sa += Dg[j][0];
                Dg[j][1] = __expf(Dg[j][1]-ma);  sa += Dg[j][1];
                Dg[j][2] = __expf(Dg[j][2]-mb);  sb += Dg[j][2];
                Dg[j][3] = __expf(Dg[j][3]-mb);  sb += Dg[j][3];
            }
            sa += __shfl_xor_sync(0xffffffffu, sa, 1);
            sa += __shfl_xor_sync(0xffffffffu, sa, 2);
            sb += __shfl_xor_sync(0xffffffffu, sb, 1);
            sb += __shfl_xor_sync(0xffffffffu, sb, 2);
            mh[0]=ma; sh[0]=sa; mh[1]=mb; sh[1]=sb;

            if ((l&3) == 0){
                #pragma unroll
                for (int h = 0; h < 2; h++){
                    int r = 16*rg + (l>>2) + 8*h;
                    ms2[kh*128 + r] = make_float2(mh[h], sh[h]);
                }
            }
            __syncthreads();

            float scl[2];
            #pragma unroll
            for (int h = 0; h < 2; h++){
                int r = 16*rg + (l>>2) + 8*h;
                float2 f0 = ms2[r], f1 = ms2[128 + r];
                float M = fmaxf(f0.x, f1.x);
                float Stot = f0.y*__expf(f0.x-M) + f1.y*__expf(f1.x-M);
                scl[h] = __expf(mh[h]-M) / Stot;
            }

            u32* ahp = (u32*)(sm+OFF_AHI);
            int r0 = 16*rg + (l>>2), r1 = r0 + 8;
            #pragma unroll
            for (int j = 0; j < 8; j++){
                int ui = 32*kh + 4*j + (l&3);
                ahp[r0*68 + ui] = pkh(tobf(Dg[j][0]*scl[0]), tobf(Dg[j][1]*scl[0]));
                ahp[r1*68 + ui] = pkh(tobf(Dg[j][2]*scl[1]), tobf(Dg[j][3]*scl[1]));
            }
        }

        // ---- prefetch next chunk's X (overlaps sync + phase 3 MMAs) ----
        {
            int ci2 = (ci + 1 < cnt) ? (ci + 1) : ci;
            const float* xr = Xb + (size_t)(st+ci2)*CH*D_;
            #pragma unroll
            for (int i = 0; i < 8; i++) pf[i] = *(const float4*)(xr + 4*i);
        }
        __syncthreads();

        // ---- phase 3 (single bf16 pass): E[k][d] += A_hi^T X_hi; colsum via ones ----
        #pragma unroll 1
        for (int s = 0; s < 8; s++){
            u32 soT = (u32)(16*RS)*s;
            u32 ah0,ah1,ah2,ah3;
            ldm4t(ah0,ah1,ah2,ah3, aAt + soT);
            #pragma unroll
            for (int p = 0; p < 4; p++){
                u32 bh0,bh1,bh2,bh3;
                ldm4t(bh0,bh1,bh2,bh3, aXt + soT + 32u*p);
                mma_bf(Eg[2*p],   ah0,ah1,ah2,ah3, bh0,bh1);
                mma_bf(Eg[2*p+1], ah0,ah1,ah2,ah3, bh2,bh3);
            }
            if (dh == 0){
                u32 b0,b1;
                ldm2t(b0,b1, aOn + soT);
                mma_bf(cs, ah0,ah1,ah2,ah3, b0,b1);
            }
        }
    }

    // ---- share colsum, then epilogue P = E - colsum*C ----
    {
        float* COLs = (float*)(sm+OFF_CS);
        if (dh == 0 && (l&3) == 0){
            COLs[16*kg + (l>>2)]     = cs[0];
            COLs[16*kg + (l>>2) + 8] = cs[2];
        }
        __syncthreads();
        float* P = g_partial + (size_t)blockIdx.x*(K_*D_);
        #pragma unroll
        for (int h = 0; h < 2; h++){
            int k = 16*kg + (l>>2) + 8*h;
            float csv = COLs[k];
            #pragma unroll
            for (int j = 0; j < 8; j++){
                int d0 = 64*dh + 8*j + 2*(l&3);
                float2 cv = *(const float2*)(C + k*D_ + d0);
                float2 o;
                o.x = Eg[j][2*h]   - csv*cv.x;
                o.y = Eg[j][2*h+1] - csv*cv.y;
                *(float2*)(P + k*D_ + d0) = o;
            }
        }
    }
}

__global__ void vq_reduce_kernel(float* __restrict__ out)
{
    int i = blockIdx.x * blockDim.x + threadIdx.x;
    if (i >= (B_*K_*D_)/4) return;
    int b = i >> 12, j = i & (K_*D_/4 - 1);
    float4 s = make_float4(0.f,0.f,0.f,0.f);
    #pragma unroll
    for (int t = 0; t < CPB; t++){
        float4 v = reinterpret_cast<const float4*>(g_partial + ((size_t)(b*CPB+t))*(K_*D_))[j];
        s.x += v.x; s.y += v.y; s.z += v.z; s.w += v.w;
    }
    reinterpret_cast<float4*>(out)[i] = s;
}

extern "C" void kernel_launch(void* const* d_in, const int* in_sizes, int n_in,
                              void* d_out, int out_size)
{
    const float *X = nullptr, *C = nullptr, *S = nullptr;
    for (int i = 0; i < n_in; i++){
        if      (in_sizes[i] == B_*N_*D_) X = (const float*)d_in[i];
        else if (in_sizes[i] == K_*D_)    C = (const float*)d_in[i];
        else if (in_sizes[i] == K_)       S = (const float*)d_in[i];
    }
    cudaFuncSetAttribute(vq_mma_kernel, cudaFuncAttributeMaxDynamicSharedMemorySize, SMEM_BYTES);
    vq_mma_kernel<<<GRID, NT, SMEM_BYTES>>>(X, C, S);
    vq_reduce_kernel<<<(B_*K_*D_/4 + 127)/128, 128>>>((float*)d_out);
}

// round 13
// speedup vs baseline: 1.0476x; 1.0476x over previous
#include <cuda_runtime.h>
#include <cuda_bf16.h>

typedef unsigned int u32; typedef unsigned short u16;

#define B_ 8
#define N_ 16384
#define D_ 128
#define K_ 128
#define CH 128
#define CPB 19
#define GRID (B_*CPB)
#define NT 512
#define CHUNKS_PER_B 128

#define RS 272                 /* tile row stride bytes = 68 u32 = 136 u16 */
#define TNM 34816              /* 128-row tile bytes */
#define OFF_X2  0
#define OFF_MS  512            /* (m,s) exchange: 2 halves x 128 rows x float2 */
#define OFF_SM2 2560
#define OFF_SSC 3072
#define OFF_SS  3584
#define OFF_CS  4096           /* colsum[128] */
#define OFF_CHI 4608
#define OFF_CLO (OFF_CHI+1*TNM)
#define OFF_XHI (OFF_CHI+2*TNM)
#define OFF_XLO (OFF_CHI+3*TNM)
#define OFF_AHI (OFF_CHI+4*TNM)
#define SMEM_BYTES (OFF_CHI+5*TNM)   /* 178688 */

#define LOG2E 1.4426950408889634f

__device__ float g_partial[(size_t)GRID*K_*D_];

static __device__ __forceinline__ u32 cvta_s(const void* p){
    u32 a; asm("{ .reg .u64 t; cvta.to.shared.u64 t, %1; cvt.u32.u64 %0, t; }":"=r"(a):"l"(p)); return a;
}
static __device__ __forceinline__ float ex2f(float x){
    float y; asm("ex2.approx.f32 %0, %1;" : "=f"(y) : "f"(x)); return y;
}
static __device__ __forceinline__ void ldm4(u32&r0,u32&r1,u32&r2,u32&r3,u32 a){
    asm volatile("ldmatrix.sync.aligned.m8n8.x4.shared.b16 {%0,%1,%2,%3}, [%4];"
        : "=r"(r0),"=r"(r1),"=r"(r2),"=r"(r3) : "r"(a));
}
static __device__ __forceinline__ void ldm4t(u32&r0,u32&r1,u32&r2,u32&r3,u32 a){
    asm volatile("ldmatrix.sync.aligned.m8n8.x4.trans.shared.b16 {%0,%1,%2,%3}, [%4];"
        : "=r"(r0),"=r"(r1),"=r"(r2),"=r"(r3) : "r"(a));
}
static __device__ __forceinline__ void ldm2t(u32&r0,u32&r1,u32 a){
    asm volatile("ldmatrix.sync.aligned.m8n8.x2.trans.shared.b16 {%0,%1}, [%2];"
        : "=r"(r0),"=r"(r1) : "r"(a));
}
static __device__ __forceinline__ void mma_bf(float* c, u32 a0,u32 a1,u32 a2,u32 a3, u32 b0,u32 b1){
    asm volatile("mma.sync.aligned.m16n8k16.row.col.f32.bf16.bf16.f32 "
        "{%0,%1,%2,%3}, {%4,%5,%6,%7}, {%8,%9}, {%0,%1,%2,%3};"
        : "+f"(c[0]),"+f"(c[1]),"+f"(c[2]),"+f"(c[3])
        : "r"(a0),"r"(a1),"r"(a2),"r"(a3),"r"(b0),"r"(b1));
}
static __device__ __forceinline__ void splitbf(float x, u16& h, u16& l){
    __nv_bfloat16 bh = __float2bfloat16(x);
    float r = x - __bfloat162float(bh);
    h = __bfloat16_as_ushort(bh);
    l = __bfloat16_as_ushort(__float2bfloat16(r));
}
static __device__ __forceinline__ u16 tobf(float x){
    return __bfloat16_as_ushort(__float2bfloat16(x));
}
static __device__ __forceinline__ u32 pkh(u16 a, u16 b){ return (u32)a | ((u32)b<<16); }

__global__ __launch_bounds__(NT, 1)
void vq_mma_kernel(const float* __restrict__ X, const float* __restrict__ C,
                   const float* __restrict__ S)
{
    extern __shared__ char sm[];
    const u32 smb = cvta_s(sm);
    const int tid = threadIdx.x, w = tid>>5, l = tid&31;
    const int rg = w&7, kh = w>>3;     // phase-1 tile: rows 16rg..+15, k-cols 64kh..+63
    const int kg = w&7, dh = w>>3;     // phase-3 tile: k-rows 16kg..+15, d-cols 64dh..+63

    // ones column in XHI padding: u16 col 128 = bf16 1.0, cols 129..135 = 0
    if (tid < 128){
        u32* row = (u32*)(sm+OFF_XHI) + tid*68;
        row[64] = 0x00003F80u; row[65] = 0u; row[66] = 0u; row[67] = 0u;
    }

    // ---- C -> Chi/Clo (k-major) + ||c||^2  (4 threads per row) ----
    {
        int k = tid>>2, q = tid&3;
        const float* cr = C + k*D_ + q*32;
        u32* dhp = (u32*)(sm+OFF_CHI) + k*68 + q*16;
        u32* dlp = (u32*)(sm+OFF_CLO) + k*68 + q*16;
        float c2 = 0.f;
        #pragma unroll
        for (int i = 0; i < 8; i++){
            float4 v = *(const float4*)(cr + 4*i);
            float xs[4] = {v.x,v.y,v.z,v.w};
            u16 hb[4], lb[4];
            #pragma unroll
            for (int e = 0; e < 4; e++){ c2 += xs[e]*xs[e]; splitbf(xs[e], hb[e], lb[e]); }
            dhp[2*i]   = pkh(hb[0],hb[1]);  dhp[2*i+1] = pkh(hb[2],hb[3]);
            dlp[2*i]   = pkh(lb[0],lb[1]);  dlp[2*i+1] = pkh(lb[2],lb[3]);
        }
        c2 += __shfl_xor_sync(0xffffffffu, c2, 1);
        c2 += __shfl_xor_sync(0xffffffffu, c2, 2);
        if (q == 0) ((float*)(sm+OFF_X2))[k] = c2;
    }
    __syncthreads();
    if (tid < K_){
        // constants pre-scaled by log2(e): logits land in log2 domain -> bare ex2
        float s = S[tid] * LOG2E, c2 = ((float*)(sm+OFF_X2))[tid];
        ((float*)(sm+OFF_SM2))[tid] = -2.f*s;
        ((float*)(sm+OFF_SSC))[tid] = s*c2;
        ((float*)(sm+OFF_SS ))[tid] = s;
    }
    __syncthreads();

    const int bb = blockIdx.x / CPB, tt = blockIdx.x % CPB;
    const int base = CHUNKS_PER_B / CPB, rem = CHUNKS_PER_B % CPB;
    const int cnt = base + (tt < rem ? 1 : 0);
    const int st  = tt*base + (tt < rem ? tt : rem);

    // lane address bases
    const u32 aX1 = smb + OFF_XHI + (u32)((16*rg + (l&15))*RS + 16*(l>>4));                  // P1 A
    const u32 aC  = smb + OFF_CHI + (u32)((64*kh + (l&7) + 8*(l>>4))*RS + 16*((l>>3)&1));    // P1 B
    const u32 aAt = smb + OFF_AHI + (u32)(((l&7) + 8*(l>>4))*RS + 32*kg + 16*((l>>3)&1));    // P3 A trans
    const u32 aXt = smb + OFF_XHI + (u32)(((l&7) + 8*((l>>3)&1))*RS + 128*dh + 16*(l>>4));   // P3 B trans
    const u32 aOn = smb + OFF_XHI + (u32)(((l&7) + 8*((l>>3)&1))*RS + 256);                  // ones col trans

    float Eg[8][4];
    float cs[4];
    cs[0]=cs[1]=cs[2]=cs[3]=0.f;
    #pragma unroll
    for (int j = 0; j < 8; j++){ Eg[j][0]=Eg[j][1]=Eg[j][2]=Eg[j][3]=0.f; }

    float2* ms2 = (float2*)(sm+OFF_MS);

    // per-thread X slice base (32 contiguous floats = one 128B line per chunk)
    const float* Xb = X + (size_t)bb*N_*D_ + (size_t)(tid>>2)*D_ + (size_t)(tid&3)*32;

    for (int ci = 0; ci < cnt; ci++){
        __syncthreads();   // prev phase-3 reads done before overwrite

        // ---- convert X chunk -> Xhi/Xlo + x2  (4 threads per row) ----
        {
            const float* xr = Xb + (size_t)(st+ci)*CH*D_;
            int n = tid>>2, q = tid&3;
            u32* dhp = (u32*)(sm+OFF_XHI) + n*68 + q*16;
            u32* dlp = (u32*)(sm+OFF_XLO) + n*68 + q*16;
            float x2 = 0.f;
            #pragma unroll
            for (int i = 0; i < 8; i++){
                float4 v = *(const float4*)(xr + 4*i);
                float xs[4] = {v.x,v.y,v.z,v.w};
                u16 hb[4], lb[4];
                #pragma unroll
                for (int e = 0; e < 4; e++){ x2 += xs[e]*xs[e]; splitbf(xs[e], hb[e], lb[e]); }
                dhp[2*i]   = pkh(hb[0],hb[1]);  dhp[2*i+1] = pkh(hb[2],hb[3]);
                dlp[2*i]   = pkh(lb[0],lb[1]);  dlp[2*i+1] = pkh(lb[2],lb[3]);
            }
            x2 += __shfl_xor_sync(0xffffffffu, x2, 1);
            x2 += __shfl_xor_sync(0xffffffffu, x2, 2);
            if (q == 0) ((float*)(sm+OFF_X2))[n] = x2;
        }
        __syncthreads();

        // ---- phase 1: logits (16 rows x 64 k per warp), 3-pass split ----
        float Dg[8][4];
        #pragma unroll
        for (int j = 0; j < 8; j++){ Dg[j][0]=Dg[j][1]=Dg[j][2]=Dg[j][3]=0.f; }

        #pragma unroll 1
        for (int s = 0; s < 8; s++){
            u32 so = 32u*s;
            u32 ah0,ah1,ah2,ah3, al0,al1,al2,al3;
            ldm4(ah0,ah1,ah2,ah3, aX1 + so);
            ldm4(al0,al1,al2,al3, aX1 + TNM + so);
            #pragma unroll
            for (int p = 0; p < 4; p++){
                u32 bo = aC + (u32)(p*16*RS) + so;
                u32 bh0,bh1,bh2,bh3, bl0,bl1,bl2,bl3;
                ldm4(bh0,bh1,bh2,bh3, bo);
                ldm4(bl0,bl1,bl2,bl3, bo + TNM);
                mma_bf(Dg[2*p],   ah0,ah1,ah2,ah3, bh0,bh1);
                mma_bf(Dg[2*p],   ah0,ah1,ah2,ah3, bl0,bl1);
                mma_bf(Dg[2*p],   al0,al1,al2,al3, bh0,bh1);
                mma_bf(Dg[2*p+1], ah0,ah1,ah2,ah3, bh2,bh3);
                mma_bf(Dg[2*p+1], ah0,ah1,ah2,ah3, bl2,bl3);
                mma_bf(Dg[2*p+1], al0,al1,al2,al3, bh2,bh3);
            }
        }

        // ---- softmax (log2 domain): scale, per-half (m,s), exchange, write A_hi ----
        {
            float x2v[2], mh[2], sh[2];
            x2v[0] = ((float*)(sm+OFF_X2))[16*rg + (l>>2)];
            x2v[1] = ((float*)(sm+OFF_X2))[16*rg + (l>>2) + 8];

            #pragma unroll
            for (int j = 0; j < 8; j++){
                int c0 = 64*kh + 8*j + 2*(l&3);
                float2 m2 = *(const float2*)(sm + OFF_SM2 + c0*4);
                float2 sc = *(const float2*)(sm + OFF_SSC + c0*4);
                float2 sv = *(const float2*)(sm + OFF_SS  + c0*4);
                Dg[j][0] = fmaf(m2.x, Dg[j][0], fmaf(sv.x, x2v[0], sc.x));
                Dg[j][1] = fmaf(m2.y, Dg[j][1], fmaf(sv.y, x2v[0], sc.y));
                Dg[j][2] = fmaf(m2.x, Dg[j][2], fmaf(sv.x, x2v[1], sc.x));
                Dg[j][3] = fmaf(m2.y, Dg[j][3], fmaf(sv.y, x2v[1], sc.y));
            }

            float ma = -1e30f, mb = -1e30f;
            #pragma unroll
            for (int j = 0; j < 8; j++){
                ma = fmaxf(ma, fmaxf(Dg[j][0], Dg[j][1]));
                mb = fmaxf(mb, fmaxf(Dg[j][2], Dg[j][3]));
            }
            ma = fmaxf(ma, __shfl_xor_sync(0xffffffffu, ma, 1));
            ma = fmaxf(ma, __shfl_xor_sync(0xffffffffu, ma, 2));
            mb = fmaxf(mb, __shfl_xor_sync(0xffffffffu, mb, 1));
            mb = fmaxf(mb, __shfl_xor_sync(0xffffffffu, mb, 2));
            float sa = 0.f, sb = 0.f;
            #pragma unroll
            for (int j = 0; j < 8; j++){
                Dg[j][0] = ex2f(Dg[j][0]-ma);  sa += Dg[j][0];
                Dg[j][1] = ex2f(Dg[j][1]-ma);  sa += Dg[j][1];
                Dg[j][2] = ex2f(Dg[j][2]-mb);  sb += Dg[j][2];
                Dg[j][3] = ex2f(Dg[j][3]-mb);  sb += Dg[j][3];
            }
            sa += __shfl_xor_sync(0xffffffffu, sa, 1);
            sa += __shfl_xor_sync(0xffffffffu, sa, 2);
            sb += __shfl_xor_sync(0xffffffffu, sb, 1);
            sb += __shfl_xor_sync(0xffffffffu, sb, 2);
            mh[0]=ma; sh[0]=sa; mh[1]=mb; sh[1]=sb;

            if ((l&3) == 0){
                #pragma unroll
                for (int h = 0; h < 2; h++){
                    int r = 16*rg + (l>>2) + 8*h;
                    ms2[kh*128 + r] = make_float2(mh[h], sh[h]);
                }
            }
            __syncthreads();

            float scl[2];
            #pragma unroll
            for (int h = 0; h < 2; h++){
                int r = 16*rg + (l>>2) + 8*h;
                float2 f0 = ms2[r], f1 = ms2[128 + r];
                float M = fmaxf(f0.x, f1.x);
                float Stot = f0.y*ex2f(f0.x-M) + f1.y*ex2f(f1.x-M);
                scl[h] = ex2f(mh[h]-M) / Stot;
            }

            u32* ahp = (u32*)(sm+OFF_AHI);
            int r0 = 16*rg + (l>>2), r1 = r0 + 8;
            #pragma unroll
            for (int j = 0; j < 8; j++){
                int ui = 32*kh + 4*j + (l&3);
                ahp[r0*68 + ui] = pkh(tobf(Dg[j][0]*scl[0]), tobf(Dg[j][1]*scl[0]));
                ahp[r1*68 + ui] = pkh(tobf(Dg[j][2]*scl[1]), tobf(Dg[j][3]*scl[1]));
            }
        }

        // ---- L2 prefetch of next chunk's X line (zero register cost) ----
        if (ci + 1 < cnt){
            const float* nx = Xb + (size_t)(st+ci+1)*CH*D_;
            asm volatile("prefetch.global.L2 [%0];" :: "l"(nx));
        }
        __syncthreads();

        // ---- phase 3 (single bf16 pass): E[k][d] += A_hi^T X_hi; colsum via ones ----
        #pragma unroll 1
        for (int s = 0; s < 8; s++){
            u32 soT = (u32)(16*RS)*s;
            u32 ah0,ah1,ah2,ah3;
            ldm4t(ah0,ah1,ah2,ah3, aAt + soT);
            #pragma unroll
            for (int p = 0; p < 4; p++){
                u32 bh0,bh1,bh2,bh3;
                ldm4t(bh0,bh1,bh2,bh3, aXt + soT + 32u*p);
                mma_bf(Eg[2*p],   ah0,ah1,ah2,ah3, bh0,bh1);
                mma_bf(Eg[2*p+1], ah0,ah1,ah2,ah3, bh2,bh3);
            }
            if (dh == 0){
                u32 b0,b1;
                ldm2t(b0,b1, aOn + soT);
                mma_bf(cs, ah0,ah1,ah2,ah3, b0,b1);
            }
        }
    }

    // ---- share colsum, then epilogue P = E - colsum*C ----
    {
        float* COLs = (float*)(sm+OFF_CS);
        if (dh == 0 && (l&3) == 0){
            COLs[16*kg + (l>>2)]     = cs[0];
            COLs[16*kg + (l>>2) + 8] = cs[2];
        }
        __syncthreads();
        float* P = g_partial + (size_t)blockIdx.x*(K_*D_);
        #pragma unroll
        for (int h = 0; h < 2; h++){
            int k = 16*kg + (l>>2) + 8*h;
            float csv = COLs[k];
            #pragma unroll
            for (int j = 0; j < 8; j++){
                int d0 = 64*dh + 8*j + 2*(l&3);
                float2 cv = *(const float2*)(C + k*D_ + d0);
                float2 o;
                o.x = Eg[j][2*h]   - csv*cv.x;
                o.y = Eg[j][2*h+1] - csv*cv.y;
                *(float2*)(P + k*D_ + d0) = o;
            }
        }
    }
}

__global__ void vq_reduce_kernel(float* __restrict__ out)
{
    int i = blockIdx.x * blockDim.x + threadIdx.x;
    if (i >= (B_*K_*D_)/4) return;
    int b = i >> 12, j = i & (K_*D_/4 - 1);
    float4 s = make_float4(0.f,0.f,0.f,0.f);
    #pragma unroll
    for (int t = 0; t < CPB; t++){
        float4 v = reinterpret_cast<const float4*>(g_partial + ((size_t)(b*CPB+t))*(K_*D_))[j];
        s.x += v.x; s.y += v.y; s.z += v.z; s.w += v.w;
    }
    reinterpret_cast<float4*>(out)[i] = s;
}

extern "C" void kernel_launch(void* const* d_in, const int* in_sizes, int n_in,
                              void* d_out, int out_size)
{
    const float *X = nullptr, *C = nullptr, *S = nullptr;
    for (int i = 0; i < n_in; i++){
        if      (in_sizes[i] == B_*N_*D_) X = (const float*)d_in[i];
        else if (in_sizes[i] == K_*D_)    C = (const float*)d_in[i];
        else if (in_sizes[i] == K_)       S = (const float*)d_in[i];
    }
    cudaFuncSetAttribute(vq_mma_kernel, cudaFuncAttributeMaxDynamicSharedMemorySize, SMEM_BYTES);
    vq_mma_kernel<<<GRID, NT, SMEM_BYTES>>>(X, C, S);
    vq_reduce_kernel<<<(B_*K_*D_/4 + 255)/256, 256>>>((float*)d_out);
}

// round 15
// speedup vs baseline: 1.3154x; 1.2556x over previous
#include <cuda_runtime.h>
#include <cuda_fp16.h>

typedef unsigned int u32; typedef unsigned short u16;

#define B_ 8
#define N_ 16384
#define D_ 128
#define K_ 128
#define CH 128
#define CPB 19
#define GRID (B_*CPB)
#define NT 512
#define CHUNKS_PER_B 128

#define RS 272                 /* tile row stride bytes = 68 u32 = 136 u16 */
#define TNM 34816              /* 128-row tile bytes */
#define OFF_X2  0
#define OFF_MS  512            /* (m,s) exchange: 2 halves x 128 rows x float2 */
#define OFF_SM2 2560
#define OFF_SSC 3072
#define OFF_SS  3584
#define OFF_CS  4096           /* colsum[128] */
#define OFF_CHI 4608
#define OFF_XHI (OFF_CHI+1*TNM)
#define OFF_AHI (OFF_CHI+2*TNM)
#define SMEM_BYTES (OFF_CHI+3*TNM)   /* 109056 */

#define LOG2E 1.4426950408889634f

__device__ float g_partial[(size_t)GRID*K_*D_];

static __device__ __forceinline__ u32 cvta_s(const void* p){
    u32 a; asm("{ .reg .u64 t; cvta.to.shared.u64 t, %1; cvt.u32.u64 %0, t; }":"=r"(a):"l"(p)); return a;
}
static __device__ __forceinline__ float ex2f(float x){
    float y; asm("ex2.approx.f32 %0, %1;" : "=f"(y) : "f"(x)); return y;
}
static __device__ __forceinline__ void ldm4(u32&r0,u32&r1,u32&r2,u32&r3,u32 a){
    asm volatile("ldmatrix.sync.aligned.m8n8.x4.shared.b16 {%0,%1,%2,%3}, [%4];"
        : "=r"(r0),"=r"(r1),"=r"(r2),"=r"(r3) : "r"(a));
}
static __device__ __forceinline__ void ldm4t(u32&r0,u32&r1,u32&r2,u32&r3,u32 a){
    asm volatile("ldmatrix.sync.aligned.m8n8.x4.trans.shared.b16 {%0,%1,%2,%3}, [%4];"
        : "=r"(r0),"=r"(r1),"=r"(r2),"=r"(r3) : "r"(a));
}
static __device__ __forceinline__ void ldm2t(u32&r0,u32&r1,u32 a){
    asm volatile("ldmatrix.sync.aligned.m8n8.x2.trans.shared.b16 {%0,%1}, [%2];"
        : "=r"(r0),"=r"(r1) : "r"(a));
}
static __device__ __forceinline__ void mma_hf(float* c, u32 a0,u32 a1,u32 a2,u32 a3, u32 b0,u32 b1){
    asm volatile("mma.sync.aligned.m16n8k16.row.col.f32.f16.f16.f32 "
        "{%0,%1,%2,%3}, {%4,%5,%6,%7}, {%8,%9}, {%0,%1,%2,%3};"
        : "+f"(c[0]),"+f"(c[1]),"+f"(c[2]),"+f"(c[3])
        : "r"(a0),"r"(a1),"r"(a2),"r"(a3),"r"(b0),"r"(b1));
}
static __device__ __forceinline__ u16 tohf(float x){
    return __half_as_ushort(__float2half(x));
}
static __device__ __forceinline__ u32 pkh(u16 a, u16 b){ return (u32)a | ((u32)b<<16); }

__global__ __launch_bounds__(NT, 1)
void vq_mma_kernel(const float* __restrict__ X, const float* __restrict__ C,
                   const float* __restrict__ S)
{
    extern __shared__ char sm[];
    const u32 smb = cvta_s(sm);
    const int tid = threadIdx.x, w = tid>>5, l = tid&31;
    const int rg = w&7, kh = w>>3;     // phase-1 tile: rows 16rg..+15, k-cols 64kh..+63
    const int kg = w&7, dh = w>>3;     // phase-3 tile: k-rows 16kg..+15, d-cols 64dh..+63

    // ones column in XHI padding: u16 col 128 = fp16 1.0, cols 129..135 = 0
    if (tid < 128){
        u32* row = (u32*)(sm+OFF_XHI) + tid*68;
        row[64] = 0x00003C00u; row[65] = 0u; row[66] = 0u; row[67] = 0u;
    }

    // ---- C -> fp16 tile (k-major) + ||c||^2  (4 threads per row) ----
    {
        int k = tid>>2, q = tid&3;
        const float* cr = C + k*D_ + q*32;
        u32* dhp = (u32*)(sm+OFF_CHI) + k*68 + q*16;
        float c2 = 0.f;
        #pragma unroll
        for (int i = 0; i < 8; i++){
            float4 v = *(const float4*)(cr + 4*i);
            c2 += v.x*v.x + v.y*v.y + v.z*v.z + v.w*v.w;
            dhp[2*i]   = pkh(tohf(v.x), tohf(v.y));
            dhp[2*i+1] = pkh(tohf(v.z), tohf(v.w));
        }
        c2 += __shfl_xor_sync(0xffffffffu, c2, 1);
        c2 += __shfl_xor_sync(0xffffffffu, c2, 2);
        if (q == 0) ((float*)(sm+OFF_X2))[k] = c2;
    }
    __syncthreads();
    if (tid < K_){
        // constants pre-scaled by log2(e): logits land in log2 domain -> bare ex2
        float s = S[tid] * LOG2E, c2 = ((float*)(sm+OFF_X2))[tid];
        ((float*)(sm+OFF_SM2))[tid] = -2.f*s;
        ((float*)(sm+OFF_SSC))[tid] = s*c2;
        ((float*)(sm+OFF_SS ))[tid] = s;
    }
    __syncthreads();

    const int bb = blockIdx.x / CPB, tt = blockIdx.x % CPB;
    const int base = CHUNKS_PER_B / CPB, rem = CHUNKS_PER_B % CPB;
    const int cnt = base + (tt < rem ? 1 : 0);
    const int st  = tt*base + (tt < rem ? tt : rem);

    // lane address bases
    const u32 aX1 = smb + OFF_XHI + (u32)((16*rg + (l&15))*RS + 16*(l>>4));                  // P1 A
    const u32 aC  = smb + OFF_CHI + (u32)((64*kh + (l&7) + 8*(l>>4))*RS + 16*((l>>3)&1));    // P1 B
    const u32 aAt = smb + OFF_AHI + (u32)(((l&7) + 8*(l>>4))*RS + 32*kg + 16*((l>>3)&1));    // P3 A trans
    const u32 aXt = smb + OFF_XHI + (u32)(((l&7) + 8*((l>>3)&1))*RS + 128*dh + 16*(l>>4));   // P3 B trans
    const u32 aOn = smb + OFF_XHI + (u32)(((l&7) + 8*((l>>3)&1))*RS + 256);                  // ones col trans

    float Eg[8][4];
    float cs[4];
    cs[0]=cs[1]=cs[2]=cs[3]=0.f;
    #pragma unroll
    for (int j = 0; j < 8; j++){ Eg[j][0]=Eg[j][1]=Eg[j][2]=Eg[j][3]=0.f; }

    float2* ms2 = (float2*)(sm+OFF_MS);

    // per-thread X slice base (32 contiguous floats = one 128B line per chunk)
    const float* Xb = X + (size_t)bb*N_*D_ + (size_t)(tid>>2)*D_ + (size_t)(tid&3)*32;

    for (int ci = 0; ci < cnt; ci++){
        __syncthreads();   // prev phase-3 reads done before overwrite

        // ---- convert X chunk -> fp16 tile + x2  (4 threads per row) ----
        {
            const float* xr = Xb + (size_t)(st+ci)*CH*D_;
            int n = tid>>2, q = tid&3;
            u32* dhp = (u32*)(sm+OFF_XHI) + n*68 + q*16;
            float x2 = 0.f;
            #pragma unroll
            for (int i = 0; i < 8; i++){
                float4 v = *(const float4*)(xr + 4*i);
                x2 += v.x*v.x + v.y*v.y + v.z*v.z + v.w*v.w;
                dhp[2*i]   = pkh(tohf(v.x), tohf(v.y));
                dhp[2*i+1] = pkh(tohf(v.z), tohf(v.w));
            }
            x2 += __shfl_xor_sync(0xffffffffu, x2, 1);
            x2 += __shfl_xor_sync(0xffffffffu, x2, 2);
            if (q == 0) ((float*)(sm+OFF_X2))[n] = x2;
        }
        __syncthreads();

        // ---- phase 1: logits (16 rows x 64 k per warp), single fp16 pass ----
        float Dg[8][4];
        #pragma unroll
        for (int j = 0; j < 8; j++){ Dg[j][0]=Dg[j][1]=Dg[j][2]=Dg[j][3]=0.f; }

        #pragma unroll 1
        for (int s = 0; s < 8; s++){
            u32 so = 32u*s;
            u32 ah0,ah1,ah2,ah3;
            ldm4(ah0,ah1,ah2,ah3, aX1 + so);
            #pragma unroll
            for (int p = 0; p < 4; p++){
                u32 bh0,bh1,bh2,bh3;
                ldm4(bh0,bh1,bh2,bh3, aC + (u32)(p*16*RS) + so);
                mma_hf(Dg[2*p],   ah0,ah1,ah2,ah3, bh0,bh1);
                mma_hf(Dg[2*p+1], ah0,ah1,ah2,ah3, bh2,bh3);
            }
        }

        // ---- softmax (log2 domain): scale, per-half (m,s), exchange, write A ----
        {
            float x2v[2], mh[2], sh[2];
            x2v[0] = ((float*)(sm+OFF_X2))[16*rg + (l>>2)];
            x2v[1] = ((float*)(sm+OFF_X2))[16*rg + (l>>2) + 8];

            #pragma unroll
            for (int j = 0; j < 8; j++){
                int c0 = 64*kh + 8*j + 2*(l&3);
                float2 m2 = *(const float2*)(sm + OFF_SM2 + c0*4);
                float2 sc = *(const float2*)(sm + OFF_SSC + c0*4);
                float2 sv = *(const float2*)(sm + OFF_SS  + c0*4);
                Dg[j][0] = fmaf(m2.x, Dg[j][0], fmaf(sv.x, x2v[0], sc.x));
                Dg[j][1] = fmaf(m2.y, Dg[j][1], fmaf(sv.y, x2v[0], sc.y));
                Dg[j][2] = fmaf(m2.x, Dg[j][2], fmaf(sv.x, x2v[1], sc.x));
                Dg[j][3] = fmaf(m2.y, Dg[j][3], fmaf(sv.y, x2v[1], sc.y));
            }

            float ma = -1e30f, mb = -1e30f;
            #pragma unroll
            for (int j = 0; j < 8; j++){
                ma = fmaxf(ma, fmaxf(Dg[j][0], Dg[j][1]));
                mb = fmaxf(mb, fmaxf(Dg[j][2], Dg[j][3]));
            }
            ma = fmaxf(ma, __shfl_xor_sync(0xffffffffu, ma, 1));
            ma = fmaxf(ma, __shfl_xor_sync(0xffffffffu, ma, 2));
            mb = fmaxf(mb, __shfl_xor_sync(0xffffffffu, mb, 1));
            mb = fmaxf(mb, __shfl_xor_sync(0xffffffffu, mb, 2));
            float sa = 0.f, sb = 0.f;
            #pragma unroll
            for (int j = 0; j < 8; j++){
                Dg[j][0] = ex2f(Dg[j][0]-ma);  sa += Dg[j][0];
                Dg[j][1] = ex2f(Dg[j][1]-ma);  sa += Dg[j][1];
                Dg[j][2] = ex2f(Dg[j][2]-mb);  sb += Dg[j][2];
                Dg[j][3] = ex2f(Dg[j][3]-mb);  sb += Dg[j][3];
            }
            sa += __shfl_xor_sync(0xffffffffu, sa, 1);
            sa += __shfl_xor_sync(0xffffffffu, sa, 2);
            sb += __shfl_xor_sync(0xffffffffu, sb, 1);
            sb += __shfl_xor_sync(0xffffffffu, sb, 2);
            mh[0]=ma; sh[0]=sa; mh[1]=mb; sh[1]=sb;

            if ((l&3) == 0){
                #pragma unroll
                for (int h = 0; h < 2; h++){
                    int r = 16*rg + (l>>2) + 8*h;
                    ms2[kh*128 + r] = make_float2(mh[h], sh[h]);
                }
            }
            __syncthreads();

            float scl[2];
            #pragma unroll
            for (int h = 0; h < 2; h++){
                int r = 16*rg + (l>>2) + 8*h;
                float2 f0 = ms2[r], f1 = ms2[128 + r];
                float M = fmaxf(f0.x, f1.x);
                float Stot = f0.y*ex2f(f0.x-M) + f1.y*ex2f(f1.x-M);
                scl[h] = ex2f(mh[h]-M) / Stot;
            }

            u32* ahp = (u32*)(sm+OFF_AHI);
            int r0 = 16*rg + (l>>2), r1 = r0 + 8;
            #pragma unroll
            for (int j = 0; j < 8; j++){
                int ui = 32*kh + 4*j + (l&3);
                ahp[r0*68 + ui] = pkh(tohf(Dg[j][0]*scl[0]), tohf(Dg[j][1]*scl[0]));
                ahp[r1*68 + ui] = pkh(tohf(Dg[j][2]*scl[1]), tohf(Dg[j][3]*scl[1]));
            }
        }

        // ---- L2 prefetch of next chunk's X line (zero register cost) ----
        if (ci + 1 < cnt){
            const float* nx = Xb + (size_t)(st+ci+1)*CH*D_;
            asm volatile("prefetch.global.L2 [%0];" :: "l"(nx));
        }
        __syncthreads();

        // ---- phase 3 (single fp16 pass): E[k][d] += A^T X; colsum via ones ----
        #pragma unroll 1
        for (int s = 0; s < 8; s++){
            u32 soT = (u32)(16*RS)*s;
            u32 ah0,ah1,ah2,ah3;
            ldm4t(ah0,ah1,ah2,ah3, aAt + soT);
            #pragma unroll
            for (int p = 0; p < 4; p++){
                u32 bh0,bh1,bh2,bh3;
                ldm4t(bh0,bh1,bh2,bh3, aXt + soT + 32u*p);
                mma_hf(Eg[2*p],   ah0,ah1,ah2,ah3, bh0,bh1);
                mma_hf(Eg[2*p+1], ah0,ah1,ah2,ah3, bh2,bh3);
            }
            if (dh == 0){
                u32 b0,b1;
                ldm2t(b0,b1, aOn + soT);
                mma_hf(cs, ah0,ah1,ah2,ah3, b0,b1);
            }
        }
    }

    // ---- share colsum, then epilogue P = E - colsum*C ----
    {
        float* COLs = (float*)(sm+OFF_CS);
        if (dh == 0 && (l&3) == 0){
            COLs[16*kg + (l>>2)]     = cs[0];
            COLs[16*kg + (l>>2) + 8] = cs[2];
        }
        __syncthreads();
        float* P = g_partial + (size_t)blockIdx.x*(K_*D_);
        #pragma unroll
        for (int h = 0; h < 2; h++){
            int k = 16*kg + (l>>2) + 8*h;
            float csv = COLs[k];
            #pragma unroll
            for (int j = 0; j < 8; j++){
                int d0 = 64*dh + 8*j + 2*(l&3);
                float2 cv = *(const float2*)(C + k*D_ + d0);
                float2 o;
                o.x = Eg[j][2*h]   - csv*cv.x;
                o.y = Eg[j][2*h+1] - csv*cv.y;
                *(float2*)(P + k*D_ + d0) = o;
            }
        }
    }
}

__global__ void vq_reduce_kernel(float* __restrict__ out)
{
    int i = blockIdx.x * blockDim.x + threadIdx.x;
    if (i >= (B_*K_*D_)/4) return;
    int b = i >> 12, j = i & (K_*D_/4 - 1);
    float4 s = make_float4(0.f,0.f,0.f,0.f);
    #pragma unroll
    for (int t = 0; t < CPB; t++){
        float4 v = reinterpret_cast<const float4*>(g_partial + ((size_t)(b*CPB+t))*(K_*D_))[j];
        s.x += v.x; s.y += v.y; s.z += v.z; s.w += v.w;
    }
    reinterpret_cast<float4*>(out)[i] = s;
}

extern "C" void kernel_launch(void* const* d_in, const int* in_sizes, int n_in,
                              void* d_out, int out_size)
{
    const float *X = nullptr, *C = nullptr, *S = nullptr;
    for (int i = 0; i < n_in; i++){
        if      (in_sizes[i] == B_*N_*D_) X = (const float*)d_in[i];
        else if (in_sizes[i] == K_*D_)    C = (const float*)d_in[i];
        else if (in_sizes[i] == K_)       S = (const float*)d_in[i];
    }
    cudaFuncSetAttribute(vq_mma_kernel, cudaFuncAttributeMaxDynamicSharedMemorySize, SMEM_BYTES);
    vq_mma_kernel<<<GRID, NT, SMEM_BYTES>>>(X, C, S);
    vq_reduce_kernel<<<(B_*K_*D_/4 + 255)/256, 256>>>((float*)d_out);
}